// round 5
// baseline (speedup 1.0000x reference)
#include <cuda_runtime.h>

#define LSEQ   2048
#define NBATCH 2
#define HID    2048
#define INTER  4096
#define NSTATE 16
#define RANK   128
#define NTOK   (NBATCH * LSEQ)        /* 4096 tokens */
#define PROJC  (2 * INTER)            /* 8192 in_proj cols */
#define SSMC   (RANK + 2 * NSTATE)    /* 160 */

// ---------------- scratch (device globals; no allocations allowed) ----------
__device__ float g_proj[(size_t)NTOK * PROJC];   // in_proj output (u | gate)
__device__ float g_u  [(size_t)NTOK * INTER];    // conv+silu output, token-major
__device__ float g_dt [(size_t)NTOK * INTER];    // softplus(dt)
__device__ float g_y  [(size_t)NTOK * INTER];    // scan output (gated)
__device__ float g_ssmp[(size_t)NTOK * SSMC];    // [dt_r | B | C]
__device__ float g_Abuf[INTER * NSTATE];         // A = -exp(A_log)

// ---------------------------------------------------------------------------
// Generic C = A * B^T SGEMM.  A: MxK row-major (lda), B: NxK row-major (ldb),
// C: MxN row-major (ldc).  BM=128 fixed, BN_/TN_ templated. 256 threads,
// TM=8 rows per thread, TXN = BN_/TN_ must equal 16.
// EPI: 0 = plain store, 1 = softplus(x + bias[col]).
// Requirements guaranteed by caller: M % 128 == 0, K % 16 == 0,
// lda/ldb % 4 == 0, base pointers 16B aligned. N handled with guards.
// ---------------------------------------------------------------------------
template<int BN_, int TN_, int EPI>
__global__ __launch_bounds__(256)
void sgemm_nt(const float* __restrict__ A, const float* __restrict__ B,
              float* __restrict__ C, const float* __restrict__ bias,
              int M, int N, int K, int lda, int ldb, int ldc)
{
    constexpr int BM = 128, BK = 16, TM = 8;
    constexpr int TXN = BN_ / TN_;              // threads along N (=16)
    static_assert(TXN * (BM / TM) == 256, "thread layout");
    constexpr int NB4 = BN_ * 4;                // float4 count in B tile
    constexpr int BITER = (NB4 + 255) / 256;

    __shared__ float As[BK][BM + 4];
    __shared__ float Bs[BK][BN_ + 4];

    const int tid = threadIdx.x;
    const int bm = blockIdx.y * BM;
    const int bn = blockIdx.x * BN_;

    const int tx = tid % TXN;
    const int ty = tid / TXN;

    float acc[TM][TN_];
#pragma unroll
    for (int i = 0; i < TM; i++)
#pragma unroll
        for (int j = 0; j < TN_; j++) acc[i][j] = 0.f;

    // A-tile loader: 512 float4 per tile, 2 per thread
    const int ar = tid >> 2;                    // 0..63
    const int ac = (tid & 3) << 2;              // 0,4,8,12
    const float* Ap0 = A + (size_t)(bm + ar) * lda + ac;
    const float* Ap1 = A + (size_t)(bm + ar + 64) * lda + ac;

    // B-tile loader precompute
    const float* Bp[BITER];
    bool bval[BITER];
    int brow[BITER], bc4[BITER];
#pragma unroll
    for (int it = 0; it < BITER; it++) {
        int idx = tid + it * 256;
        brow[it] = idx >> 2;
        bc4[it]  = (idx & 3) << 2;
        int gn = bn + brow[it];
        bval[it] = (idx < NB4) && (gn < N);
        Bp[it] = B + (size_t)(gn < N ? gn : 0) * ldb + bc4[it];
    }

    for (int k0 = 0; k0 < K; k0 += BK) {
        float4 a0 = *(const float4*)(Ap0 + k0);
        float4 a1 = *(const float4*)(Ap1 + k0);
        float4 breg[BITER];
#pragma unroll
        for (int it = 0; it < BITER; it++)
            breg[it] = bval[it] ? *(const float4*)(Bp[it] + k0)
                                : make_float4(0.f, 0.f, 0.f, 0.f);

        __syncthreads();
        As[ac + 0][ar] = a0.x; As[ac + 1][ar] = a0.y;
        As[ac + 2][ar] = a0.z; As[ac + 3][ar] = a0.w;
        As[ac + 0][ar + 64] = a1.x; As[ac + 1][ar + 64] = a1.y;
        As[ac + 2][ar + 64] = a1.z; As[ac + 3][ar + 64] = a1.w;
#pragma unroll
        for (int it = 0; it < BITER; it++) {
            int idx = tid + it * 256;
            if (idx < NB4) {
                Bs[bc4[it] + 0][brow[it]] = breg[it].x;
                Bs[bc4[it] + 1][brow[it]] = breg[it].y;
                Bs[bc4[it] + 2][brow[it]] = breg[it].z;
                Bs[bc4[it] + 3][brow[it]] = breg[it].w;
            }
        }
        __syncthreads();

#pragma unroll
        for (int kk = 0; kk < BK; kk++) {
            float4 af0 = *(const float4*)(&As[kk][ty * TM]);
            float4 af1 = *(const float4*)(&As[kk][ty * TM + 4]);
            float af[TM] = {af0.x, af0.y, af0.z, af0.w,
                            af1.x, af1.y, af1.z, af1.w};
            float bf[TN_];
            if constexpr (TN_ % 4 == 0) {
#pragma unroll
                for (int j4 = 0; j4 < TN_ / 4; j4++) {
                    float4 b4 = *(const float4*)(&Bs[kk][tx * TN_ + j4 * 4]);
                    bf[j4 * 4 + 0] = b4.x; bf[j4 * 4 + 1] = b4.y;
                    bf[j4 * 4 + 2] = b4.z; bf[j4 * 4 + 3] = b4.w;
                }
            } else {
#pragma unroll
                for (int j = 0; j < TN_; j++) bf[j] = Bs[kk][tx * TN_ + j];
            }
#pragma unroll
            for (int i = 0; i < TM; i++)
#pragma unroll
                for (int j = 0; j < TN_; j++)
                    acc[i][j] = fmaf(af[i], bf[j], acc[i][j]);
        }
    }

#pragma unroll
    for (int i = 0; i < TM; i++) {
        int row = bm + ty * TM + i;
#pragma unroll
        for (int j = 0; j < TN_; j++) {
            int col = bn + tx * TN_ + j;
            if (col < N) {
                float v = acc[i][j];
                if (EPI == 1) {
                    v += bias[col];
                    v = (v > 20.f) ? v : log1pf(expf(v));   // softplus
                }
                C[(size_t)row * ldc + col] = v;
            }
        }
    }
}

// ---------------------------------------------------------------------------
// Depthwise causal conv1d (K=4) + SiLU, token-major layout.
// out[b,l,d] = silu(cb[d] + sum_k cw[d,k] * u_in[b, l-3+k, d])
// ---------------------------------------------------------------------------
__global__ __launch_bounds__(256)
void conv_silu_kernel(const float* __restrict__ proj,
                      const float* __restrict__ cw,
                      const float* __restrict__ cb,
                      float* __restrict__ u)
{
    const int d = blockIdx.x * 256 + threadIdx.x;
    const int r = blockIdx.y;               // b*L + l
    const int l = r & (LSEQ - 1);
    const float* p = proj + (size_t)r * PROJC + d;
    const float w0 = cw[4 * d + 0], w1 = cw[4 * d + 1];
    const float w2 = cw[4 * d + 2], w3 = cw[4 * d + 3];
    float acc = cb[d] + w3 * p[0];
    if (l >= 1) acc += w2 * p[-PROJC];
    if (l >= 2) acc += w1 * p[-2 * PROJC];
    if (l >= 3) acc += w0 * p[-3 * PROJC];
    float s = acc / (1.f + __expf(-acc));
    u[(size_t)r * INTER + d] = s;
}

// A = -exp(A_log)
__global__ void prep_A_kernel(const float* __restrict__ alog,
                              float* __restrict__ A)
{
    int i = blockIdx.x * 256 + threadIdx.x;
    if (i < INTER * NSTATE) A[i] = -expf(alog[i]);
}

// ---------------------------------------------------------------------------
// Selective scan: one thread per (batch, channel d). 2048 sequential steps,
// 16 states in registers. Fused epilogue: (+u*D) * silu(gate).
// ---------------------------------------------------------------------------
__global__ __launch_bounds__(64)
void scan_kernel(const float* __restrict__ dt, const float* __restrict__ u,
                 const float* __restrict__ ssmp,
                 const float* __restrict__ proj,     // gate at col INTER+d
                 const float* __restrict__ A, const float* __restrict__ Dv,
                 float* __restrict__ y)
{
    const int g = blockIdx.x * 64 + threadIdx.x;   // 0..B*INTER-1
    const int batch = g / INTER;
    const int d = g % INTER;

    float a[NSTATE];
#pragma unroll
    for (int n = 0; n < NSTATE; n++) a[n] = A[d * NSTATE + n];
    const float Dd = Dv[d];

    float s[NSTATE];
#pragma unroll
    for (int n = 0; n < NSTATE; n++) s[n] = 0.f;

    const size_t rbase = (size_t)batch * LSEQ;
    for (int l = 0; l < LSEQ; l++) {
        const size_t r = rbase + l;
        const float dtv = dt[r * INTER + d];
        const float uv  = u[r * INTER + d];
        const float4* bc = (const float4*)(ssmp + r * SSMC + RANK);
        float Bv[NSTATE], Cv[NSTATE];
#pragma unroll
        for (int t = 0; t < 4; t++) {
            float4 q = bc[t];
            Bv[4 * t + 0] = q.x; Bv[4 * t + 1] = q.y;
            Bv[4 * t + 2] = q.z; Bv[4 * t + 3] = q.w;
            float4 c = bc[4 + t];
            Cv[4 * t + 0] = c.x; Cv[4 * t + 1] = c.y;
            Cv[4 * t + 2] = c.z; Cv[4 * t + 3] = c.w;
        }
        const float dtu = dtv * uv;
        float yv = 0.f;
#pragma unroll
        for (int n = 0; n < NSTATE; n++) {
            float dA = __expf(dtv * a[n]);
            s[n] = fmaf(dA, s[n], dtu * Bv[n]);
            yv = fmaf(s[n], Cv[n], yv);
        }
        const float gt = proj[r * PROJC + INTER + d];
        const float sg = gt / (1.f + __expf(-gt));
        y[r * INTER + d] = (yv + uv * Dd) * sg;
    }
}

// ---------------------------------------------------------------------------
extern "C" void kernel_launch(void* const* d_in, const int* in_sizes, int n_in,
                              void* d_out, int out_size)
{
    const float* hs   = (const float*)d_in[0];  // (B, L, HID)
    const float* inw  = (const float*)d_in[1];  // (2*INTER, HID)
    const float* cw   = (const float*)d_in[2];  // (INTER, 1, 4)
    const float* cb   = (const float*)d_in[3];  // (INTER,)
    const float* xw   = (const float*)d_in[4];  // (160, INTER)
    const float* dtw  = (const float*)d_in[5];  // (INTER, RANK)
    const float* dtb  = (const float*)d_in[6];  // (INTER,)
    const float* alog = (const float*)d_in[7];  // (INTER, 16)
    const float* Dp   = (const float*)d_in[8];  // (INTER,)
    const float* ow   = (const float*)d_in[9];  // (HID, INTER)
    float* out = (float*)d_out;
    (void)in_sizes; (void)n_in; (void)out_size;

    float *proj, *u, *dt, *y, *ssmp, *Abuf;
    cudaGetSymbolAddress((void**)&proj, g_proj);
    cudaGetSymbolAddress((void**)&u,    g_u);
    cudaGetSymbolAddress((void**)&dt,   g_dt);
    cudaGetSymbolAddress((void**)&y,    g_y);
    cudaGetSymbolAddress((void**)&ssmp, g_ssmp);
    cudaGetSymbolAddress((void**)&Abuf, g_Abuf);

    // 1) in_proj: proj(4096 x 8192) = hs(4096 x 2048) @ inw^T
    sgemm_nt<128, 8, 0><<<dim3(PROJC / 128, NTOK / 128), 256>>>(
        hs, inw, proj, nullptr, NTOK, PROJC, HID, HID, HID, PROJC);

    // 2) depthwise conv + silu -> u (token-major)
    conv_silu_kernel<<<dim3(INTER / 256, NTOK), 256>>>(proj, cw, cb, u);

    // 3) A = -exp(A_log)
    prep_A_kernel<<<(INTER * NSTATE) / 256, 256>>>(alog, Abuf);

    // 4) x_proj: ssmp(4096 x 160) = u(4096 x 4096) @ xw^T   (skinny-N tile)
    sgemm_nt<32, 2, 0><<<dim3((SSMC + 31) / 32, NTOK / 128), 256>>>(
        u, xw, ssmp, nullptr, NTOK, SSMC, INTER, INTER, INTER, SSMC);

    // 5) dt: dt(4096 x 4096) = ssmp[:, :128] @ dtw^T, + bias, softplus
    sgemm_nt<128, 8, 1><<<dim3(INTER / 128, NTOK / 128), 256>>>(
        ssmp, dtw, dt, dtb, NTOK, INTER, RANK, SSMC, RANK, INTER);

    // 6) selective scan + skip + gate
    scan_kernel<<<(NBATCH * INTER) / 64, 64>>>(dt, u, ssmp, proj, Abuf, Dp, y);

    // 7) out_proj: out(4096 x 2048) = y(4096 x 4096) @ ow^T
    sgemm_nt<128, 8, 0><<<dim3(HID / 128, NTOK / 128), 256>>>(
        y, ow, out, nullptr, NTOK, HID, INTER, INTER, INTER, HID);
}

// round 11
// speedup vs baseline: 2.0759x; 2.0759x over previous
#include <cuda_runtime.h>
#include <cuda_bf16.h>
#include <cstdint>

#define LSEQ   2048
#define NBATCH 2
#define HID    2048
#define INTER  4096
#define NSTATE 16
#define RANK   128
#define NTOK   (NBATCH * LSEQ)        /* 4096 tokens */
#define PROJC  (2 * INTER)            /* 8192 in_proj cols */
#define SSMC   (RANK + 2 * NSTATE)    /* 160 */

// ---------------- fp32 scratch ----------------------------------------------
__device__ __align__(256) float g_proj[(size_t)NTOK * PROJC];
__device__ __align__(256) float g_u  [(size_t)NTOK * INTER];
__device__ __align__(256) float g_dt [(size_t)NTOK * INTER];
__device__ __align__(256) float g_ssmp[(size_t)NTOK * SSMC];
__device__ __align__(256) float g_Abuf[INTER * NSTATE];

// ---------------- bf16 split scratch (hi/lo pairs) --------------------------
__device__ __align__(256) __nv_bfloat16 g_hsH[(size_t)NTOK * HID],   g_hsL[(size_t)NTOK * HID];
__device__ __align__(256) __nv_bfloat16 g_wiH[(size_t)PROJC * HID],  g_wiL[(size_t)PROJC * HID];
__device__ __align__(256) __nv_bfloat16 g_uH [(size_t)NTOK * INTER], g_uL [(size_t)NTOK * INTER];
__device__ __align__(256) __nv_bfloat16 g_xwH[(size_t)SSMC * INTER], g_xwL[(size_t)SSMC * INTER];
__device__ __align__(256) __nv_bfloat16 g_spH[(size_t)NTOK * SSMC],  g_spL[(size_t)NTOK * SSMC];
__device__ __align__(256) __nv_bfloat16 g_dwH[(size_t)INTER * RANK], g_dwL[(size_t)INTER * RANK];
__device__ __align__(256) __nv_bfloat16 g_yH [(size_t)NTOK * INTER], g_yL [(size_t)NTOK * INTER];
__device__ __align__(256) __nv_bfloat16 g_owH[(size_t)HID * INTER],  g_owL[(size_t)HID * INTER];

// ---------------- PTX helpers ------------------------------------------------
__device__ __forceinline__ uint32_t s2u(const void* p) {
    uint32_t a;
    asm("{ .reg .u64 t; cvta.to.shared.u64 t, %1; cvt.u32.u64 %0, t; }"
        : "=r"(a) : "l"(p));
    return a;
}

__device__ __forceinline__ void ldsm4(uint32_t* r, uint32_t addr) {
    asm volatile("ldmatrix.sync.aligned.m8n8.x4.shared.b16 {%0,%1,%2,%3}, [%4];"
                 : "=r"(r[0]), "=r"(r[1]), "=r"(r[2]), "=r"(r[3]) : "r"(addr));
}
__device__ __forceinline__ void mma_bf16(float* d, const uint32_t* a, const uint32_t* b) {
    asm volatile(
        "mma.sync.aligned.m16n8k16.row.col.f32.bf16.bf16.f32 "
        "{%0,%1,%2,%3}, {%4,%5,%6,%7}, {%8,%9}, {%0,%1,%2,%3};"
        : "+f"(d[0]), "+f"(d[1]), "+f"(d[2]), "+f"(d[3])
        : "r"(a[0]), "r"(a[1]), "r"(a[2]), "r"(a[3]), "r"(b[0]), "r"(b[1]));
}

// ---------------------------------------------------------------------------
// fp32 -> (bf16 hi, bf16 lo) split
// ---------------------------------------------------------------------------
__global__ __launch_bounds__(256)
void split_kernel(const float* __restrict__ x, __nv_bfloat16* __restrict__ hi,
                  __nv_bfloat16* __restrict__ lo, int n)
{
    int i = blockIdx.x * 256 + threadIdx.x;
    if (i < n) {
        float v = x[i];
        __nv_bfloat16 h = __float2bfloat16(v);
        hi[i] = h;
        lo[i] = __float2bfloat16(v - __bfloat162float(h));
    }
}

// ---------------------------------------------------------------------------
// HMMA bf16x3 GEMM: C(MxN fp32) = A(MxK) * B(NxK)^T where A,B given as
// bf16 hi/lo splits; accumulates Ah*Bh + Ah*Bl + Al*Bh in fp32.
// CTA 128x128, BK=32, 8 warps (2M x 4N) of 64x32, 3-stage cp.async pipeline.
// B stored [N][K] row-major = col-major KxN, so B fragments use ldmatrix
// WITHOUT .trans (b0 must pack 2 consecutive k for one n).
// EPI: 0 plain store, 1 softplus(x + bias[col]).
// Requires M%128==0, K%32==0; N guarded.
// ---------------------------------------------------------------------------
#define STG_BYTES 40960          /* 4 * 128 * 80 */
#define TILE_B    10240          /* 128 * 80 */

template<int EPI>
__global__ __launch_bounds__(256)
void mma_gemm(const __nv_bfloat16* __restrict__ Ah, const __nv_bfloat16* __restrict__ Al,
              const __nv_bfloat16* __restrict__ Bh, const __nv_bfloat16* __restrict__ Bl,
              float* __restrict__ C, const float* __restrict__ bias,
              int M, int N, int K, int lda, int ldb, int ldc)
{
    extern __shared__ char smem[];
    const int tid = threadIdx.x;
    const int lane = tid & 31;
    const int w = tid >> 5;
    const int wm = w & 1;               // 2 warps along M
    const int wn = w >> 1;              // 4 warps along N
    const int bm = blockIdx.y * 128;
    const int bn = blockIdx.x * 128;
    const int nIter = K >> 5;
    const int bn_rows = N - bn;
    const uint32_t sbase = s2u(smem);

    float acc[4][4][4];
#pragma unroll
    for (int mi = 0; mi < 4; mi++)
#pragma unroll
        for (int ni = 0; ni < 4; ni++)
#pragma unroll
            for (int q = 0; q < 4; q++) acc[mi][ni][q] = 0.f;

    // ---- loader: one BK=32 chunk of all 4 operand tiles into stage it%3 ----
    auto load_stage = [&](int it) {
        const uint32_t stb = sbase + (uint32_t)(it % 3) * STG_BYTES;
        const int k0 = it << 5;
#pragma unroll
        for (int j = 0; j < 8; j++) {
            int idx = tid + j * 256;            // 0..2047
            int op  = idx >> 9;                 // 0:Ah 1:Al 2:Bh 3:Bl
            int rem = idx & 511;
            int row = rem >> 2;
            int ch  = rem & 3;
            bool isB = (op >= 2);
            const __nv_bfloat16* base = (op == 0) ? Ah : (op == 1) ? Al
                                      : (op == 2) ? Bh : Bl;
            bool v = !isB || (row < bn_rows);
            int grow = (isB ? bn : bm) + (v ? row : 0);
            int ld = isB ? ldb : lda;
            const void* src = base + (size_t)grow * ld + k0 + ch * 8;
            uint32_t dst = stb + (uint32_t)op * TILE_B + (uint32_t)(row * 80 + ch * 16);
            uint32_t sz = v ? 16u : 0u;
            asm volatile("cp.async.cg.shared.global [%0], [%1], 16, %2;"
                         :: "r"(dst), "l"(src), "r"(sz));
        }
        asm volatile("cp.async.commit_group;" ::: "memory");
    };

    load_stage(0);
    if (nIter > 1) load_stage(1);
    if (nIter > 2) load_stage(2);

    const int r8 = lane & 7;
    const int t8 = lane >> 3;
    const int half = lane >> 4;
    const int sub = (lane >> 3) & 1;

    for (int it = 0; it < nIter; it++) {
        if (it + 2 < nIter)      asm volatile("cp.async.wait_group 2;" ::: "memory");
        else if (it + 1 < nIter) asm volatile("cp.async.wait_group 1;" ::: "memory");
        else                     asm volatile("cp.async.wait_group 0;" ::: "memory");
        __syncthreads();

        const uint32_t stb = sbase + (uint32_t)(it % 3) * STG_BYTES;
#pragma unroll
        for (int kk = 0; kk < 32; kk += 16) {
            uint32_t ah[4][4], al[4][4], bh[4][2], bl[4][2];
            // A fragments: matrices (m0-7,k0),(m8-15,k0),(m0-7,k8),(m8-15,k8)
#pragma unroll
            for (int mi = 0; mi < 4; mi++) {
                int row = wm * 64 + mi * 16 + (t8 & 1) * 8 + r8;
                int col = kk + (t8 >> 1) * 8;
                uint32_t off = (uint32_t)(row * 80 + col * 2);
                ldsm4(ah[mi], stb + off);
                ldsm4(al[mi], stb + TILE_B + off);
            }
            // B fragments (NON-trans; [N][K] storage is col-major KxN):
            // matrices (n0-7,k0),(n0-7,k8),(n8-15,k0),(n8-15,k8)
#pragma unroll
            for (int ng = 0; ng < 2; ng++) {
                int row = wn * 32 + ng * 16 + half * 8 + r8;
                int col = kk + sub * 8;
                uint32_t off = (uint32_t)(row * 80 + col * 2);
                uint32_t t[4];
                ldsm4(t, stb + 2 * TILE_B + off);
                bh[2 * ng][0] = t[0]; bh[2 * ng][1] = t[1];
                bh[2 * ng + 1][0] = t[2]; bh[2 * ng + 1][1] = t[3];
                ldsm4(t, stb + 3 * TILE_B + off);
                bl[2 * ng][0] = t[0]; bl[2 * ng][1] = t[1];
                bl[2 * ng + 1][0] = t[2]; bl[2 * ng + 1][1] = t[3];
            }
#pragma unroll
            for (int mi = 0; mi < 4; mi++)
#pragma unroll
                for (int ni = 0; ni < 4; ni++) {
                    mma_bf16(acc[mi][ni], ah[mi], bh[ni]);
                    mma_bf16(acc[mi][ni], ah[mi], bl[ni]);
                    mma_bf16(acc[mi][ni], al[mi], bh[ni]);
                }
        }
        __syncthreads();
        if (it + 3 < nIter) load_stage(it + 3);
    }

    // ---- epilogue ----
    const int g = lane >> 2;
    const int t4 = lane & 3;
#pragma unroll
    for (int mi = 0; mi < 4; mi++) {
#pragma unroll
        for (int h8 = 0; h8 < 2; h8++) {
            int row = bm + wm * 64 + mi * 16 + h8 * 8 + g;
            size_t rb = (size_t)row * ldc;
#pragma unroll
            for (int ni = 0; ni < 4; ni++) {
                int col = bn + wn * 32 + ni * 8 + t4 * 2;
                float v0 = acc[mi][ni][h8 * 2 + 0];
                float v1 = acc[mi][ni][h8 * 2 + 1];
                if (EPI == 1) {
                    v0 += (col < N) ? bias[col] : 0.f;
                    v1 += (col + 1 < N) ? bias[col + 1] : 0.f;
                    v0 = (v0 > 20.f) ? v0 : log1pf(expf(v0));
                    v1 = (v1 > 20.f) ? v1 : log1pf(expf(v1));
                }
                if (col < N)     C[rb + col] = v0;
                if (col + 1 < N) C[rb + col + 1] = v1;
            }
        }
    }
}

// ---------------------------------------------------------------------------
// Depthwise causal conv1d (K=4) + SiLU; emits fp32 u AND bf16 hi/lo split.
// ---------------------------------------------------------------------------
__global__ __launch_bounds__(256)
void conv_silu_kernel(const float* __restrict__ proj,
                      const float* __restrict__ cw,
                      const float* __restrict__ cb,
                      float* __restrict__ u,
                      __nv_bfloat16* __restrict__ uH,
                      __nv_bfloat16* __restrict__ uL)
{
    const int d = blockIdx.x * 256 + threadIdx.x;
    const int r = blockIdx.y;               // b*L + l
    const int l = r & (LSEQ - 1);
    const float* p = proj + (size_t)r * PROJC + d;
    const float w0 = cw[4 * d + 0], w1 = cw[4 * d + 1];
    const float w2 = cw[4 * d + 2], w3 = cw[4 * d + 3];
    float acc = cb[d] + w3 * p[0];
    if (l >= 1) acc += w2 * p[-PROJC];
    if (l >= 2) acc += w1 * p[-2 * PROJC];
    if (l >= 3) acc += w0 * p[-3 * PROJC];
    float s = acc / (1.f + __expf(-acc));
    size_t o = (size_t)r * INTER + d;
    u[o] = s;
    __nv_bfloat16 h = __float2bfloat16(s);
    uH[o] = h;
    uL[o] = __float2bfloat16(s - __bfloat162float(h));
}

__global__ void prep_A_kernel(const float* __restrict__ alog, float* __restrict__ A)
{
    int i = blockIdx.x * 256 + threadIdx.x;
    if (i < INTER * NSTATE) A[i] = -expf(alog[i]);
}

// ---------------------------------------------------------------------------
// Selective scan with next-step register prefetch. Emits y directly as
// bf16 hi/lo (only consumer is out_proj).
// ---------------------------------------------------------------------------
__global__ __launch_bounds__(64)
void scan_kernel(const float* __restrict__ dt, const float* __restrict__ u,
                 const float* __restrict__ ssmp,
                 const float* __restrict__ proj,     // gate at col INTER+d
                 const float* __restrict__ A, const float* __restrict__ Dv,
                 __nv_bfloat16* __restrict__ yH, __nv_bfloat16* __restrict__ yL)
{
    const int g = blockIdx.x * 64 + threadIdx.x;   // 0..B*INTER-1
    const int batch = g / INTER;
    const int d = g % INTER;

    float a[NSTATE];
#pragma unroll
    for (int n = 0; n < NSTATE; n++) a[n] = A[d * NSTATE + n];
    const float Dd = Dv[d];

    float s[NSTATE];
#pragma unroll
    for (int n = 0; n < NSTATE; n++) s[n] = 0.f;

    const size_t rbase = (size_t)batch * LSEQ;

    float dtv, uv, gt;
    float4 pb[8];
    {
        const size_t r = rbase;
        dtv = dt[r * INTER + d];
        uv  = u[r * INTER + d];
        gt  = proj[r * PROJC + INTER + d];
        const float4* bc = (const float4*)(ssmp + r * SSMC + RANK);
#pragma unroll
        for (int t = 0; t < 8; t++) pb[t] = bc[t];
    }

    for (int l = 0; l < LSEQ; l++) {
        const float cdt = dtv, cu = uv, cgt = gt;
        float4 cb[8];
#pragma unroll
        for (int t = 0; t < 8; t++) cb[t] = pb[t];

        if (l + 1 < LSEQ) {
            const size_t r = rbase + l + 1;
            dtv = dt[r * INTER + d];
            uv  = u[r * INTER + d];
            gt  = proj[r * PROJC + INTER + d];
            const float4* bc = (const float4*)(ssmp + r * SSMC + RANK);
#pragma unroll
            for (int t = 0; t < 8; t++) pb[t] = bc[t];
        }

        float Bv[NSTATE], Cv[NSTATE];
#pragma unroll
        for (int t = 0; t < 4; t++) {
            Bv[4 * t + 0] = cb[t].x; Bv[4 * t + 1] = cb[t].y;
            Bv[4 * t + 2] = cb[t].z; Bv[4 * t + 3] = cb[t].w;
            Cv[4 * t + 0] = cb[4 + t].x; Cv[4 * t + 1] = cb[4 + t].y;
            Cv[4 * t + 2] = cb[4 + t].z; Cv[4 * t + 3] = cb[4 + t].w;
        }
        const float dtu = cdt * cu;
        float yv = 0.f;
#pragma unroll
        for (int n = 0; n < NSTATE; n++) {
            float dA = __expf(cdt * a[n]);
            s[n] = fmaf(dA, s[n], dtu * Bv[n]);
            yv = fmaf(s[n], Cv[n], yv);
        }
        const float sg = cgt / (1.f + __expf(-cgt));
        const float yo = (yv + cu * Dd) * sg;
        const size_t o = (rbase + l) * INTER + d;
        __nv_bfloat16 h = __float2bfloat16(yo);
        yH[o] = h;
        yL[o] = __float2bfloat16(yo - __bfloat162float(h));
    }
}

// ---------------------------------------------------------------------------
extern "C" void kernel_launch(void* const* d_in, const int* in_sizes, int n_in,
                              void* d_out, int out_size)
{
    const float* hs   = (const float*)d_in[0];  // (B, L, HID)
    const float* inw  = (const float*)d_in[1];  // (2*INTER, HID)
    const float* cw   = (const float*)d_in[2];  // (INTER, 1, 4)
    const float* cb   = (const float*)d_in[3];  // (INTER,)
    const float* xw   = (const float*)d_in[4];  // (160, INTER)
    const float* dtw  = (const float*)d_in[5];  // (INTER, RANK)
    const float* dtb  = (const float*)d_in[6];  // (INTER,)
    const float* alog = (const float*)d_in[7];  // (INTER, 16)
    const float* Dp   = (const float*)d_in[8];  // (INTER,)
    const float* ow   = (const float*)d_in[9];  // (HID, INTER)
    float* out = (float*)d_out;
    (void)in_sizes; (void)n_in; (void)out_size;

    float *proj, *u, *dt, *ssmp, *Abuf;
    cudaGetSymbolAddress((void**)&proj, g_proj);
    cudaGetSymbolAddress((void**)&u,    g_u);
    cudaGetSymbolAddress((void**)&dt,   g_dt);
    cudaGetSymbolAddress((void**)&ssmp, g_ssmp);
    cudaGetSymbolAddress((void**)&Abuf, g_Abuf);

    __nv_bfloat16 *hsH,*hsL,*wiH,*wiL,*uH,*uL,*xwH,*xwL,*spH,*spL,*dwH,*dwL,*yH,*yL,*owH,*owL;
    cudaGetSymbolAddress((void**)&hsH, g_hsH); cudaGetSymbolAddress((void**)&hsL, g_hsL);
    cudaGetSymbolAddress((void**)&wiH, g_wiH); cudaGetSymbolAddress((void**)&wiL, g_wiL);
    cudaGetSymbolAddress((void**)&uH,  g_uH);  cudaGetSymbolAddress((void**)&uL,  g_uL);
    cudaGetSymbolAddress((void**)&xwH, g_xwH); cudaGetSymbolAddress((void**)&xwL, g_xwL);
    cudaGetSymbolAddress((void**)&spH, g_spH); cudaGetSymbolAddress((void**)&spL, g_spL);
    cudaGetSymbolAddress((void**)&dwH, g_dwH); cudaGetSymbolAddress((void**)&dwL, g_dwL);
    cudaGetSymbolAddress((void**)&yH,  g_yH);  cudaGetSymbolAddress((void**)&yL,  g_yL);
    cudaGetSymbolAddress((void**)&owH, g_owH); cudaGetSymbolAddress((void**)&owL, g_owL);

    const int DYNSMEM = 3 * STG_BYTES;          // 122880 bytes
    cudaFuncSetAttribute(mma_gemm<0>, cudaFuncAttributeMaxDynamicSharedMemorySize, DYNSMEM);
    cudaFuncSetAttribute(mma_gemm<1>, cudaFuncAttributeMaxDynamicSharedMemorySize, DYNSMEM);

    auto split = [&](const float* x, __nv_bfloat16* h, __nv_bfloat16* l, int n) {
        split_kernel<<<(n + 255) / 256, 256>>>(x, h, l, n);
    };

    // 1) bf16 splits for in_proj operands
    split(hs,  hsH, hsL, NTOK * HID);
    split(inw, wiH, wiL, PROJC * HID);

    // 2) in_proj: proj(4096 x 8192) = hs @ inw^T
    mma_gemm<0><<<dim3(PROJC / 128, NTOK / 128), 256, DYNSMEM>>>(
        hsH, hsL, wiH, wiL, proj, nullptr, NTOK, PROJC, HID, HID, HID, PROJC);

    // 3) conv + silu -> u fp32 + bf16 split
    conv_silu_kernel<<<dim3(INTER / 256, NTOK), 256>>>(proj, cw, cb, u, uH, uL);

    // 4) A = -exp(A_log)
    prep_A_kernel<<<(INTER * NSTATE) / 256, 256>>>(alog, Abuf);

    // 5) x_proj: ssmp(4096 x 160) = u @ xw^T
    split(xw, xwH, xwL, SSMC * INTER);
    mma_gemm<0><<<dim3((SSMC + 127) / 128, NTOK / 128), 256, DYNSMEM>>>(
        uH, uL, xwH, xwL, ssmp, nullptr, NTOK, SSMC, INTER, INTER, INTER, SSMC);

    // 6) dt: dt(4096 x 4096) = ssmp[:, :128] @ dtw^T, +bias, softplus
    split(ssmp, spH, spL, NTOK * SSMC);
    split(dtw,  dwH, dwL, INTER * RANK);
    mma_gemm<1><<<dim3(INTER / 128, NTOK / 128), 256, DYNSMEM>>>(
        spH, spL, dwH, dwL, dt, dtb, NTOK, INTER, RANK, SSMC, RANK, INTER);

    // 7) selective scan + skip + gate -> y (bf16 split directly)
    scan_kernel<<<(NBATCH * INTER) / 64, 64>>>(dt, u, ssmp, proj, Abuf, Dp, yH, yL);

    // 8) out_proj: out(4096 x 2048) = y @ ow^T
    split(ow, owH, owL, HID * INTER);
    mma_gemm<0><<<dim3(HID / 128, NTOK / 128), 256, DYNSMEM>>>(
        yH, yL, owH, owL, out, nullptr, NTOK, HID, INTER, INTER, INTER, HID);
}

// round 13
// speedup vs baseline: 2.2591x; 1.0882x over previous
#include <cuda_runtime.h>
#include <cuda_bf16.h>
#include <cstdint>

#define LSEQ   2048
#define NBATCH 2
#define HID    2048
#define INTER  4096
#define NSTATE 16
#define RANK   128
#define NTOK   (NBATCH * LSEQ)        /* 4096 tokens */
#define PROJC  (2 * INTER)            /* 8192 in_proj cols */
#define SSMC   (RANK + 2 * NSTATE)    /* 160 */

// ---------------- fp32 scratch ----------------------------------------------
__device__ __align__(256) float g_proj[(size_t)NTOK * PROJC];
__device__ __align__(256) float g_u  [(size_t)NTOK * INTER];
__device__ __align__(256) float g_dt [(size_t)NTOK * INTER];
__device__ __align__(256) float g_ssmp[(size_t)NTOK * SSMC];
__device__ __align__(256) float g_Abuf[INTER * NSTATE];

// ---------------- bf16 split scratch (hi/lo pairs) --------------------------
__device__ __align__(256) __nv_bfloat16 g_hsH[(size_t)NTOK * HID],   g_hsL[(size_t)NTOK * HID];
__device__ __align__(256) __nv_bfloat16 g_wiH[(size_t)PROJC * HID],  g_wiL[(size_t)PROJC * HID];
__device__ __align__(256) __nv_bfloat16 g_uH [(size_t)NTOK * INTER], g_uL [(size_t)NTOK * INTER];
__device__ __align__(256) __nv_bfloat16 g_xwH[(size_t)SSMC * INTER], g_xwL[(size_t)SSMC * INTER];
__device__ __align__(256) __nv_bfloat16 g_spH[(size_t)NTOK * SSMC],  g_spL[(size_t)NTOK * SSMC];
__device__ __align__(256) __nv_bfloat16 g_dwH[(size_t)INTER * RANK], g_dwL[(size_t)INTER * RANK];
__device__ __align__(256) __nv_bfloat16 g_yH [(size_t)NTOK * INTER], g_yL [(size_t)NTOK * INTER];
__device__ __align__(256) __nv_bfloat16 g_owH[(size_t)HID * INTER],  g_owL[(size_t)HID * INTER];

// ---------------- PTX helpers ------------------------------------------------
__device__ __forceinline__ uint32_t s2u(const void* p) {
    uint32_t a;
    asm("{ .reg .u64 t; cvta.to.shared.u64 t, %1; cvt.u32.u64 %0, t; }"
        : "=r"(a) : "l"(p));
    return a;
}

__device__ __forceinline__ void ldsm4(uint32_t* r, uint32_t addr) {
    asm volatile("ldmatrix.sync.aligned.m8n8.x4.shared.b16 {%0,%1,%2,%3}, [%4];"
                 : "=r"(r[0]), "=r"(r[1]), "=r"(r[2]), "=r"(r[3]) : "r"(addr));
}
__device__ __forceinline__ void mma_bf16(float* d, const uint32_t* a, const uint32_t* b) {
    asm volatile(
        "mma.sync.aligned.m16n8k16.row.col.f32.bf16.bf16.f32 "
        "{%0,%1,%2,%3}, {%4,%5,%6,%7}, {%8,%9}, {%0,%1,%2,%3};"
        : "+f"(d[0]), "+f"(d[1]), "+f"(d[2]), "+f"(d[3])
        : "r"(a[0]), "r"(a[1]), "r"(a[2]), "r"(a[3]), "r"(b[0]), "r"(b[1]));
}

// ---------------------------------------------------------------------------
// fp32 -> (bf16 hi, bf16 lo) split
// ---------------------------------------------------------------------------
__global__ __launch_bounds__(256)
void split_kernel(const float* __restrict__ x, __nv_bfloat16* __restrict__ hi,
                  __nv_bfloat16* __restrict__ lo, int n)
{
    int i = blockIdx.x * 256 + threadIdx.x;
    if (i < n) {
        float v = x[i];
        __nv_bfloat16 h = __float2bfloat16(v);
        hi[i] = h;
        lo[i] = __float2bfloat16(v - __bfloat162float(h));
    }
}

// ---------------------------------------------------------------------------
// HMMA bf16x3 GEMM: C(MxN fp32) = A(MxK) * B(NxK)^T where A,B given as
// bf16 hi/lo splits; accumulates Ah*Bh + Ah*Bl + Al*Bh in fp32.
// CTA 128x128, BK=64, 8 warps (2M x 4N) of 64x32, 3-stage cp.async pipeline
// with load-before-MMA and ONE __syncthreads per stage (the iter-it load
// targets ring slot (it-1)%3, which the top-of-iteration sync proves free).
// B stored [N][K] row-major = col-major KxN, so B fragments use ldmatrix
// WITHOUT .trans. Row stride 144B keeps ldmatrix conflict-free.
// EPI: 0 plain store, 1 softplus(x + bias[col]).
// Requires M%128==0, K%64==0; N guarded.
// ---------------------------------------------------------------------------
#define ROWB      144            /* 64*2 + 16 pad */
#define TILE_B    18432          /* 128 * 144 */
#define STG_BYTES 73728          /* 4 * TILE_B */

template<int EPI>
__global__ __launch_bounds__(256)
void mma_gemm(const __nv_bfloat16* __restrict__ Ah, const __nv_bfloat16* __restrict__ Al,
              const __nv_bfloat16* __restrict__ Bh, const __nv_bfloat16* __restrict__ Bl,
              float* __restrict__ C, const float* __restrict__ bias,
              int M, int N, int K, int lda, int ldb, int ldc)
{
    extern __shared__ char smem[];
    const int tid = threadIdx.x;
    const int lane = tid & 31;
    const int w = tid >> 5;
    const int wm = w & 1;               // 2 warps along M
    const int wn = w >> 1;              // 4 warps along N
    const int bm = blockIdx.y * 128;
    const int bn = blockIdx.x * 128;
    const int nIter = K >> 6;           // BK = 64
    const int bn_rows = N - bn;
    const uint32_t sbase = s2u(smem);

    float acc[4][4][4];
#pragma unroll
    for (int mi = 0; mi < 4; mi++)
#pragma unroll
        for (int ni = 0; ni < 4; ni++)
#pragma unroll
            for (int q = 0; q < 4; q++) acc[mi][ni][q] = 0.f;

    // ---- loader: one BK=64 chunk of all 4 operand tiles into stage it%3 ----
    // 4 tiles x 128 rows x 8 chunks(16B) = 4096 cp.asyncs, 16 per thread.
    auto load_stage = [&](int it) {
        const uint32_t stb = sbase + (uint32_t)(it % 3) * STG_BYTES;
        const int k0 = it << 6;
#pragma unroll
        for (int j = 0; j < 16; j++) {
            int idx = tid + j * 256;            // 0..4095
            int op  = idx >> 10;                // 0:Ah 1:Al 2:Bh 3:Bl
            int rem = idx & 1023;
            int row = rem >> 3;
            int ch  = rem & 7;
            bool isB = (op >= 2);
            const __nv_bfloat16* base = (op == 0) ? Ah : (op == 1) ? Al
                                      : (op == 2) ? Bh : Bl;
            bool v = !isB || (row < bn_rows);
            int grow = (isB ? bn : bm) + (v ? row : 0);
            int ld = isB ? ldb : lda;
            const void* src = base + (size_t)grow * ld + k0 + ch * 8;
            uint32_t dst = stb + (uint32_t)op * TILE_B + (uint32_t)(row * ROWB + ch * 16);
            uint32_t sz = v ? 16u : 0u;
            asm volatile("cp.async.cg.shared.global [%0], [%1], 16, %2;"
                         :: "r"(dst), "l"(src), "r"(sz));
        }
        asm volatile("cp.async.commit_group;" ::: "memory");
    };

    load_stage(0);
    if (nIter > 1) load_stage(1);

    const int r8 = lane & 7;
    const int t8 = lane >> 3;
    const int half = lane >> 4;
    const int sub = (lane >> 3) & 1;

    for (int it = 0; it < nIter; it++) {
        if (it + 1 < nIter) asm volatile("cp.async.wait_group 1;" ::: "memory");
        else                asm volatile("cp.async.wait_group 0;" ::: "memory");
        __syncthreads();
        // prefetch next+1 stage now; its ring slot (it-1)%3 was freed by the
        // sync above (all warps finished iter it-1's MMAs to reach it).
        if (it + 2 < nIter) load_stage(it + 2);

        const uint32_t stb = sbase + (uint32_t)(it % 3) * STG_BYTES;
#pragma unroll
        for (int kk = 0; kk < 64; kk += 16) {
            uint32_t ah[4][4], al[4][4], bh[4][2], bl[4][2];
            // A fragments: matrices (m0-7,k0),(m8-15,k0),(m0-7,k8),(m8-15,k8)
#pragma unroll
            for (int mi = 0; mi < 4; mi++) {
                int row = wm * 64 + mi * 16 + (t8 & 1) * 8 + r8;
                int col = kk + (t8 >> 1) * 8;
                uint32_t off = (uint32_t)(row * ROWB + col * 2);
                ldsm4(ah[mi], stb + off);
                ldsm4(al[mi], stb + TILE_B + off);
            }
            // B fragments (NON-trans; [N][K] storage is col-major KxN):
            // matrices (n0-7,k0),(n0-7,k8),(n8-15,k0),(n8-15,k8)
#pragma unroll
            for (int ng = 0; ng < 2; ng++) {
                int row = wn * 32 + ng * 16 + half * 8 + r8;
                int col = kk + sub * 8;
                uint32_t off = (uint32_t)(row * ROWB + col * 2);
                uint32_t t[4];
                ldsm4(t, stb + 2 * TILE_B + off);
                bh[2 * ng][0] = t[0]; bh[2 * ng][1] = t[1];
                bh[2 * ng + 1][0] = t[2]; bh[2 * ng + 1][1] = t[3];
                ldsm4(t, stb + 3 * TILE_B + off);
                bl[2 * ng][0] = t[0]; bl[2 * ng][1] = t[1];
                bl[2 * ng + 1][0] = t[2]; bl[2 * ng + 1][1] = t[3];
            }
#pragma unroll
            for (int mi = 0; mi < 4; mi++)
#pragma unroll
                for (int ni = 0; ni < 4; ni++) {
                    mma_bf16(acc[mi][ni], ah[mi], bh[ni]);
                    mma_bf16(acc[mi][ni], ah[mi], bl[ni]);
                    mma_bf16(acc[mi][ni], al[mi], bh[ni]);
                }
        }
        // no trailing sync: next iteration's top sync provides the barrier
    }

    // ---- epilogue ----
    const int g = lane >> 2;
    const int t4 = lane & 3;
#pragma unroll
    for (int mi = 0; mi < 4; mi++) {
#pragma unroll
        for (int h8 = 0; h8 < 2; h8++) {
            int row = bm + wm * 64 + mi * 16 + h8 * 8 + g;
            size_t rb = (size_t)row * ldc;
#pragma unroll
            for (int ni = 0; ni < 4; ni++) {
                int col = bn + wn * 32 + ni * 8 + t4 * 2;
                float v0 = acc[mi][ni][h8 * 2 + 0];
                float v1 = acc[mi][ni][h8 * 2 + 1];
                if (EPI == 1) {
                    v0 += (col < N) ? bias[col] : 0.f;
                    v1 += (col + 1 < N) ? bias[col + 1] : 0.f;
                    v0 = (v0 > 20.f) ? v0 : log1pf(expf(v0));
                    v1 = (v1 > 20.f) ? v1 : log1pf(expf(v1));
                }
                if (col < N)     C[rb + col] = v0;
                if (col + 1 < N) C[rb + col + 1] = v1;
            }
        }
    }
}

// ---------------------------------------------------------------------------
// Depthwise causal conv1d (K=4) + SiLU; emits fp32 u AND bf16 hi/lo split.
// ---------------------------------------------------------------------------
__global__ __launch_bounds__(256)
void conv_silu_kernel(const float* __restrict__ proj,
                      const float* __restrict__ cw,
                      const float* __restrict__ cb,
                      float* __restrict__ u,
                      __nv_bfloat16* __restrict__ uH,
                      __nv_bfloat16* __restrict__ uL)
{
    const int d = blockIdx.x * 256 + threadIdx.x;
    const int r = blockIdx.y;               // b*L + l
    const int l = r & (LSEQ - 1);
    const float* p = proj + (size_t)r * PROJC + d;
    const float w0 = cw[4 * d + 0], w1 = cw[4 * d + 1];
    const float w2 = cw[4 * d + 2], w3 = cw[4 * d + 3];
    float acc = cb[d] + w3 * p[0];
    if (l >= 1) acc += w2 * p[-PROJC];
    if (l >= 2) acc += w1 * p[-2 * PROJC];
    if (l >= 3) acc += w0 * p[-3 * PROJC];
    float s = acc / (1.f + __expf(-acc));
    size_t o = (size_t)r * INTER + d;
    u[o] = s;
    __nv_bfloat16 h = __float2bfloat16(s);
    uH[o] = h;
    uL[o] = __float2bfloat16(s - __bfloat162float(h));
}

__global__ void prep_A_kernel(const float* __restrict__ alog, float* __restrict__ A)
{
    int i = blockIdx.x * 256 + threadIdx.x;
    if (i < INTER * NSTATE) A[i] = -expf(alog[i]);
}

// ---------------------------------------------------------------------------
// Selective scan with next-step register prefetch. Emits y directly as
// bf16 hi/lo (only consumer is out_proj).
// ---------------------------------------------------------------------------
__global__ __launch_bounds__(64)
void scan_kernel(const float* __restrict__ dt, const float* __restrict__ u,
                 const float* __restrict__ ssmp,
                 const float* __restrict__ proj,     // gate at col INTER+d
                 const float* __restrict__ A, const float* __restrict__ Dv,
                 __nv_bfloat16* __restrict__ yH, __nv_bfloat16* __restrict__ yL)
{
    const int g = blockIdx.x * 64 + threadIdx.x;   // 0..B*INTER-1
    const int batch = g / INTER;
    const int d = g % INTER;

    float a[NSTATE];
#pragma unroll
    for (int n = 0; n < NSTATE; n++) a[n] = A[d * NSTATE + n];
    const float Dd = Dv[d];

    float s[NSTATE];
#pragma unroll
    for (int n = 0; n < NSTATE; n++) s[n] = 0.f;

    const size_t rbase = (size_t)batch * LSEQ;

    float dtv, uv, gt;
    float4 pb[8];
    {
        const size_t r = rbase;
        dtv = dt[r * INTER + d];
        uv  = u[r * INTER + d];
        gt  = proj[r * PROJC + INTER + d];
        const float4* bc = (const float4*)(ssmp + r * SSMC + RANK);
#pragma unroll
        for (int t = 0; t < 8; t++) pb[t] = bc[t];
    }

    for (int l = 0; l < LSEQ; l++) {
        const float cdt = dtv, cu = uv, cgt = gt;
        float4 cb[8];
#pragma unroll
        for (int t = 0; t < 8; t++) cb[t] = pb[t];

        if (l + 1 < LSEQ) {
            const size_t r = rbase + l + 1;
            dtv = dt[r * INTER + d];
            uv  = u[r * INTER + d];
            gt  = proj[r * PROJC + INTER + d];
            const float4* bc = (const float4*)(ssmp + r * SSMC + RANK);
#pragma unroll
            for (int t = 0; t < 8; t++) pb[t] = bc[t];
        }

        float Bv[NSTATE], Cv[NSTATE];
#pragma unroll
        for (int t = 0; t < 4; t++) {
            Bv[4 * t + 0] = cb[t].x; Bv[4 * t + 1] = cb[t].y;
            Bv[4 * t + 2] = cb[t].z; Bv[4 * t + 3] = cb[t].w;
            Cv[4 * t + 0] = cb[4 + t].x; Cv[4 * t + 1] = cb[4 + t].y;
            Cv[4 * t + 2] = cb[4 + t].z; Cv[4 * t + 3] = cb[4 + t].w;
        }
        const float dtu = cdt * cu;
        float yv = 0.f;
#pragma unroll
        for (int n = 0; n < NSTATE; n++) {
            float dA = __expf(cdt * a[n]);
            s[n] = fmaf(dA, s[n], dtu * Bv[n]);
            yv = fmaf(s[n], Cv[n], yv);
        }
        const float sg = cgt / (1.f + __expf(-cgt));
        const float yo = (yv + cu * Dd) * sg;
        const size_t o = (rbase + l) * INTER + d;
        __nv_bfloat16 h = __float2bfloat16(yo);
        yH[o] = h;
        yL[o] = __float2bfloat16(yo - __bfloat162float(h));
    }
}

// ---------------------------------------------------------------------------
extern "C" void kernel_launch(void* const* d_in, const int* in_sizes, int n_in,
                              void* d_out, int out_size)
{
    const float* hs   = (const float*)d_in[0];  // (B, L, HID)
    const float* inw  = (const float*)d_in[1];  // (2*INTER, HID)
    const float* cw   = (const float*)d_in[2];  // (INTER, 1, 4)
    const float* cb   = (const float*)d_in[3];  // (INTER,)
    const float* xw   = (const float*)d_in[4];  // (160, INTER)
    const float* dtw  = (const float*)d_in[5];  // (INTER, RANK)
    const float* dtb  = (const float*)d_in[6];  // (INTER,)
    const float* alog = (const float*)d_in[7];  // (INTER, 16)
    const float* Dp   = (const float*)d_in[8];  // (INTER,)
    const float* ow   = (const float*)d_in[9];  // (HID, INTER)
    float* out = (float*)d_out;
    (void)in_sizes; (void)n_in; (void)out_size;

    float *proj, *u, *dt, *ssmp, *Abuf;
    cudaGetSymbolAddress((void**)&proj, g_proj);
    cudaGetSymbolAddress((void**)&u,    g_u);
    cudaGetSymbolAddress((void**)&dt,   g_dt);
    cudaGetSymbolAddress((void**)&ssmp, g_ssmp);
    cudaGetSymbolAddress((void**)&Abuf, g_Abuf);

    __nv_bfloat16 *hsH,*hsL,*wiH,*wiL,*uH,*uL,*xwH,*xwL,*spH,*spL,*dwH,*dwL,*yH,*yL,*owH,*owL;
    cudaGetSymbolAddress((void**)&hsH, g_hsH); cudaGetSymbolAddress((void**)&hsL, g_hsL);
    cudaGetSymbolAddress((void**)&wiH, g_wiH); cudaGetSymbolAddress((void**)&wiL, g_wiL);
    cudaGetSymbolAddress((void**)&uH,  g_uH);  cudaGetSymbolAddress((void**)&uL,  g_uL);
    cudaGetSymbolAddress((void**)&xwH, g_xwH); cudaGetSymbolAddress((void**)&xwL, g_xwL);
    cudaGetSymbolAddress((void**)&spH, g_spH); cudaGetSymbolAddress((void**)&spL, g_spL);
    cudaGetSymbolAddress((void**)&dwH, g_dwH); cudaGetSymbolAddress((void**)&dwL, g_dwL);
    cudaGetSymbolAddress((void**)&yH,  g_yH);  cudaGetSymbolAddress((void**)&yL,  g_yL);
    cudaGetSymbolAddress((void**)&owH, g_owH); cudaGetSymbolAddress((void**)&owL, g_owL);

    const int DYNSMEM = 3 * STG_BYTES;          // 221184 bytes
    cudaFuncSetAttribute(mma_gemm<0>, cudaFuncAttributeMaxDynamicSharedMemorySize, DYNSMEM);
    cudaFuncSetAttribute(mma_gemm<1>, cudaFuncAttributeMaxDynamicSharedMemorySize, DYNSMEM);

    auto split = [&](const float* x, __nv_bfloat16* h, __nv_bfloat16* l, int n) {
        split_kernel<<<(n + 255) / 256, 256>>>(x, h, l, n);
    };

    // 1) bf16 splits for in_proj operands
    split(hs,  hsH, hsL, NTOK * HID);
    split(inw, wiH, wiL, PROJC * HID);

    // 2) in_proj: proj(4096 x 8192) = hs @ inw^T
    mma_gemm<0><<<dim3(PROJC / 128, NTOK / 128), 256, DYNSMEM>>>(
        hsH, hsL, wiH, wiL, proj, nullptr, NTOK, PROJC, HID, HID, HID, PROJC);

    // 3) conv + silu -> u fp32 + bf16 split
    conv_silu_kernel<<<dim3(INTER / 256, NTOK), 256>>>(proj, cw, cb, u, uH, uL);

    // 4) A = -exp(A_log)
    prep_A_kernel<<<(INTER * NSTATE) / 256, 256>>>(alog, Abuf);

    // 5) x_proj: ssmp(4096 x 160) = u @ xw^T
    split(xw, xwH, xwL, SSMC * INTER);
    mma_gemm<0><<<dim3((SSMC + 127) / 128, NTOK / 128), 256, DYNSMEM>>>(
        uH, uL, xwH, xwL, ssmp, nullptr, NTOK, SSMC, INTER, INTER, INTER, SSMC);

    // 6) dt: dt(4096 x 4096) = ssmp[:, :128] @ dtw^T, +bias, softplus
    split(ssmp, spH, spL, NTOK * SSMC);
    split(dtw,  dwH, dwL, INTER * RANK);
    mma_gemm<1><<<dim3(INTER / 128, NTOK / 128), 256, DYNSMEM>>>(
        spH, spL, dwH, dwL, dt, dtb, NTOK, INTER, RANK, SSMC, RANK, INTER);

    // 7) selective scan + skip + gate -> y (bf16 split directly)
    scan_kernel<<<(NBATCH * INTER) / 64, 64>>>(dt, u, ssmp, proj, Abuf, Dp, yH, yL);

    // 8) out_proj: out(4096 x 2048) = y @ ow^T
    split(ow, owH, owL, HID * INTER);
    mma_gemm<0><<<dim3(HID / 128, NTOK / 128), 256, DYNSMEM>>>(
        yH, yL, owH, owL, out, nullptr, NTOK, HID, INTER, INTER, INTER, HID);
}